// round 14
// baseline (speedup 1.0000x reference)
#include <cuda_runtime.h>
#include <cuda_fp16.h>
#include <math_constants.h>
#include <cstdint>

// Problem constants
#define ROWS 2048     // B*N
#define D    128
#define E    64
#define NJ   256
#define TR   4        // rows per block in update kernel (4-way split-k, 512 thr)
#define PITCH 144     // sT row pitch in bytes (128B data + 16B skew)

__device__ float g_agg[ROWS * 2 * D];   // per row: [agg_mean(128) | agg_max(128)]
__device__ int   g_probe;               // probe scratch

__device__ __forceinline__ uint32_t pack_h2(float a, float b) {
    __half2 h = __floats2half2_rn(a, b);
    return *(uint32_t*)&h;
}

__device__ __forceinline__ uint32_t smem_u32(const void* p) {
    uint32_t a;
    asm("{ .reg .u64 t; cvta.to.shared.u64 t, %1; cvt.u32.u64 %0, t; }"
        : "=r"(a) : "l"(p));
    return a;
}

// D = A(16x16) * B(16x8) + D, fp16 in / fp32 acc. Emits HMMA.16816 on sm_103.
__device__ __forceinline__ void mma16816(float c[4], const uint32_t a[4],
                                         uint32_t b0, uint32_t b1) {
    asm volatile(
        "mma.sync.aligned.m16n8k16.row.col.f32.f16.f16.f32 "
        "{%0,%1,%2,%3}, {%4,%5,%6,%7}, {%8,%9}, {%0,%1,%2,%3};"
        : "+f"(c[0]), "+f"(c[1]), "+f"(c[2]), "+f"(c[3])
        : "r"(a[0]), "r"(a[1]), "r"(a[2]), "r"(a[3]), "r"(b0), "r"(b1));
}

// Two 8x8 b16 matrices: B fragment {b0,b1} for one k-step of m16n8k16.
__device__ __forceinline__ void ldmB(uint32_t& b0, uint32_t& b1, uint32_t addr) {
    asm volatile("ldmatrix.sync.aligned.m8n8.x2.shared.b16 {%0,%1}, [%2];"
                 : "=r"(b0), "=r"(b1) : "r"(addr));
}

// sigmoid(z + b2) given ha = 0.5*z + 0.5*b2   (1 MUFU)
__device__ __forceinline__ float sig_half(float ha) {
    float t;
    asm("tanh.approx.f32 %0, %1;" : "=f"(t) : "f"(ha));
    return fmaf(t, 0.5f, 0.5f);
}

__device__ __forceinline__ float tanh_ap(float x) {
    float t;
    asm("tanh.approx.f32 %0, %1;" : "=f"(t) : "f"(x));
    return t;
}

// ---------------------------------------------------------------------------
// Gate kernel: ONE row per CTA (grid=2048), 256 threads (8 warps).
// Warp w owns d-tile [16w,16w+16). B fragments via ldmatrix; j-tile loop is
// 2-way software-pipelined (independent accumulators).
// ---------------------------------------------------------------------------
__global__ void __launch_bounds__(256)
gate_kernel(const float* __restrict__ h, const float* __restrict__ ef,
            const unsigned int* __restrict__ adj,
            const float* __restrict__ W1, const float* __restrict__ b1,
            const float* __restrict__ W2, const float* __restrict__ b2) {
    __shared__ __align__(16) char  sT[NJ * PITCH];   // fp16 T tile, skewed rows
    __shared__ __align__(16) float sE[NJ * 4];       // edge feats, float4/row
    __shared__ float sH[D];
    __shared__ float sPp[4][E];                      // P partials
    __shared__ float sP[E];
    __shared__ int   sJ[NJ];
    __shared__ int   sW[8];

    const int tid  = threadIdx.x;
    const int w    = tid >> 5;
    const int lane = tid & 31;
    const int g    = lane >> 2;      // groupID
    const int t4   = lane & 3;       // thread-in-group
    const int row  = blockIdx.x;

    // ---- issue ALL dram loads up front (overlap with compute below) ----
    const float* efr = ef + (size_t)row * (NJ * 3);
    const float e0 = efr[tid];
    const float e1 = efr[tid + 256];
    const float e2 = efr[tid + 512];
    const int   m0 = (adj[(size_t)row * NJ + tid] != 0u);
    if (tid < D) sH[tid] = h[(size_t)row * D + tid];

    // ballot per warp (j = tid exactly covers 0..255)
    const unsigned bal = __ballot_sync(0xffffffffu, m0);
    if (lane == 0) sW[w] = __popc(bal);

    // ---- A fragments: A[d][k] = W2[k][d], one m-tile per warp (L1/L2 hot) ----
    uint32_t afr[4][4];
    {
        const int d0 = w * 16 + g;
#pragma unroll
        for (int ks = 0; ks < 4; ks++) {
            const int k0 = ks * 16 + 2 * t4;
            afr[ks][0] = pack_h2(W2[k0 * D + d0],       W2[(k0 + 1) * D + d0]);
            afr[ks][1] = pack_h2(W2[k0 * D + d0 + 8],   W2[(k0 + 1) * D + d0 + 8]);
            afr[ks][2] = pack_h2(W2[(k0 + 8) * D + d0], W2[(k0 + 9) * D + d0]);
            afr[ks][3] = pack_h2(W2[(k0 + 8) * D + d0 + 8], W2[(k0 + 9) * D + d0 + 8]);
        }
    }
    int   dsl[2];
    float hb2[2];
#pragma unroll
    for (int i = 0; i < 2; i++) {
        dsl[i] = w * 16 + g + i * 8;
        hb2[i] = 0.5f * b2[dsl[i]];
    }

    // ---- stash ef into padded smem ----
    sE[(tid / 3) * 4 + (tid % 3)]                 = e0;
    sE[((tid + 256) / 3) * 4 + ((tid + 256) % 3)] = e1;
    sE[((tid + 512) / 3) * 4 + ((tid + 512) % 3)] = e2;

    // T-build constants (k-pair = lane)
    const int k0p = 2 * lane;
    const float2 w1e0 = *(const float2*)(W1 + 128 * E + k0p);
    const float2 w1e1 = *(const float2*)(W1 + 129 * E + k0p);
    const float2 w1e2 = *(const float2*)(W1 + 130 * E + k0p);

    // ldmatrix base address (lanes 0-15 meaningful)
    const uint32_t sT_u32 = smem_u32(sT);
    const uint32_t lm_base = sT_u32 + (uint32_t)((lane & 7) * PITCH)
                                    + ((lane & 8) ? 16u : 0u);

    __syncthreads();   // sH, sW ready

    // ---- P partials: thread (kk, part) does 32-d slice ----
    {
        const int kk = tid & 63, part = tid >> 6;
        const int db = part * 32;
        float p = 0.f;
#pragma unroll 8
        for (int d = 0; d < 32; d++)
            p = fmaf(sH[db + d], __ldg(&W1[(db + d) * E + kk]), p);
        sPp[part][kk] = p;
    }

    // ---- order-preserving compaction ----
    int base = 0, cnt = 0;
#pragma unroll
    for (int ww = 0; ww < 8; ww++) {
        if (ww < w) base += sW[ww];
        cnt += sW[ww];
    }
    if (m0) sJ[base + __popc(bal & ((1u << lane) - 1u))] = tid;
    __syncthreads();   // sPp, sJ ready

    if (tid < E)
        sP[tid] = b1[tid] + ((sPp[0][tid] + sPp[1][tid]) +
                             (sPp[2][tid] + sPp[3][tid]));
    __syncthreads();   // sP ready

    if (cnt == 0) {
        if (tid < D) {
            g_agg[(size_t)row * (2 * D) + tid]     = 0.f;
            g_agg[(size_t)row * (2 * D) + D + tid] = 0.f;
        }
        return;
    }

    // ---- T build: T[s][k] = relu(P[k] + e·W1e), fp16x2 per lane ----
    {
        const float2 P2 = *(const float2*)(sP + k0p);
        for (int s = w; s < cnt; s += 8) {
            const int j = sJ[s];
            const float4 e = *(const float4*)(sE + 4 * j);
            float v0 = fmaf(e.z, w1e2.x, fmaf(e.y, w1e1.x, fmaf(e.x, w1e0.x, P2.x)));
            float v1 = fmaf(e.z, w1e2.y, fmaf(e.y, w1e1.y, fmaf(e.x, w1e0.y, P2.y)));
            *(uint32_t*)(sT + s * PITCH + lane * 4) =
                pack_h2(fmaxf(v0, 0.f), fmaxf(v1, 0.f));
        }
    }
    __syncthreads();   // sT ready

    // ---- mma over j-tiles of 8, 2-way software-pipelined ----
    float st[2] = {0.f, 0.f};                          // sum of tanh
    float zx[2] = {-CUDART_INF_F, -CUDART_INF_F};
    float zn[2] = { CUDART_INF_F,  CUDART_INF_F};
    const int ntile = (cnt + 7) >> 3;

#define EPILOG(JT, CC) do {                                                   \
        const int s0 = (JT) * 8 + 2 * t4;                                     \
        if (s0 < cnt) {                                                       \
            { const float _z = (CC)[0];                                       \
              st[0] += tanh_ap(fmaf(_z, 0.5f, hb2[0]));                       \
              zx[0] = fmaxf(zx[0], _z); zn[0] = fminf(zn[0], _z); }           \
            { const float _z = (CC)[2];                                       \
              st[1] += tanh_ap(fmaf(_z, 0.5f, hb2[1]));                       \
              zx[1] = fmaxf(zx[1], _z); zn[1] = fminf(zn[1], _z); }           \
        }                                                                     \
        if (s0 + 1 < cnt) {                                                   \
            { const float _z = (CC)[1];                                       \
              st[0] += tanh_ap(fmaf(_z, 0.5f, hb2[0]));                       \
              zx[0] = fmaxf(zx[0], _z); zn[0] = fminf(zn[0], _z); }           \
            { const float _z = (CC)[3];                                       \
              st[1] += tanh_ap(fmaf(_z, 0.5f, hb2[1]));                       \
              zx[1] = fmaxf(zx[1], _z); zn[1] = fminf(zn[1], _z); }           \
        }                                                                     \
    } while (0)

    int jt = 0;
    for (; jt + 1 < ntile; jt += 2) {
        float cA[4] = {0.f, 0.f, 0.f, 0.f};
        float cB[4] = {0.f, 0.f, 0.f, 0.f};
        const uint32_t aA = lm_base + (uint32_t)(jt * (8 * PITCH));
        const uint32_t aB = aA + (uint32_t)(8 * PITCH);
#pragma unroll
        for (int ks = 0; ks < 4; ks++) {
            uint32_t b0a, b1a, b0b, b1b;
            ldmB(b0a, b1a, aA + ks * 32);
            ldmB(b0b, b1b, aB + ks * 32);
            mma16816(cA, afr[ks], b0a, b1a);
            mma16816(cB, afr[ks], b0b, b1b);
        }
        EPILOG(jt, cA);
        EPILOG(jt + 1, cB);
    }
    if (jt < ntile) {
        float cA[4] = {0.f, 0.f, 0.f, 0.f};
        const uint32_t aA = lm_base + (uint32_t)(jt * (8 * PITCH));
#pragma unroll
        for (int ks = 0; ks < 4; ks++) {
            uint32_t b0a, b1a;
            ldmB(b0a, b1a, aA + ks * 32);
            mma16816(cA, afr[ks], b0a, b1a);
        }
        EPILOG(jt, cA);
    }
#undef EPILOG

    // 4-lane (t4 group) reduction
#pragma unroll
    for (int off = 1; off <= 2; off <<= 1) {
#pragma unroll
        for (int i = 0; i < 2; i++) {
            st[i] += __shfl_xor_sync(0xffffffffu, st[i], off);
            zx[i] = fmaxf(zx[i], __shfl_xor_sync(0xffffffffu, zx[i], off));
            zn[i] = fminf(zn[i], __shfl_xor_sync(0xffffffffu, zn[i], off));
        }
    }
    if (t4 == 0) {
        const float cntf = (float)cnt;
#pragma unroll
        for (int i = 0; i < 2; i++) {
            const int d = dsl[i];
            const float hd = sH[d];
            const float sumg = fmaf(0.5f, st[i], 0.5f * cntf); // Σσ = ½Σtanh + ½cnt
            const float cm = hd * sumg / cntf;
            const float gx = sig_half(fmaf(zx[i], 0.5f, hb2[i]));
            const float gn = sig_half(fmaf(zn[i], 0.5f, hb2[i]));
            const float cx = (hd >= 0.f) ? hd * gx : hd * gn;
            g_agg[(size_t)row * (2 * D) + d]     = cm;
            g_agg[(size_t)row * (2 * D) + D + d] = cx;
        }
    }
}

// ---------------------------------------------------------------------------
// Update MLP + residual + LayerNorm — unchanged (validated).
// ---------------------------------------------------------------------------
__global__ void __launch_bounds__(512)
update_kernel(const float* __restrict__ h,
              const float* __restrict__ U1, const float* __restrict__ b3,
              const float* __restrict__ U2, const float* __restrict__ b4,
              const float* __restrict__ gamma, const float* __restrict__ beta,
              float* __restrict__ out) {
    const int rbase = blockIdx.x * TR;
    const int tid  = threadIdx.x;
    const int d    = tid & 127;
    const int quar = tid >> 7;
    __shared__ __align__(16) float sa[TR][3 * D];     // [h | mean | max]   6KB
    __shared__ __align__(16) float sy[TR][D];         // relu hidden        2KB
    __shared__ __align__(16) float sacc[4][TR][D];    // split-k partials   8KB

    for (int idx = tid; idx < TR * 3 * D; idx += 512) {
        const int r = idx / (3 * D);
        const int m = idx % (3 * D);
        float v;
        if (m < D) v = h[(rbase + r) * D + m];
        else       v = g_agg[(size_t)(rbase + r) * (2 * D) + (m - D)];
        sa[r][m] = v;
    }
    __syncthreads();

    float acc[TR];
    {
        const float init = quar ? 0.f : b3[d];
#pragma unroll
        for (int r = 0; r < TR; r++) acc[r] = init;
    }
    const int m0 = quar * 96;
#pragma unroll 4
    for (int g4 = 0; g4 < 24; g4++) {
        const int m = m0 + g4 * 4;
        const float u0 = U1[(m + 0) * D + d];
        const float u1 = U1[(m + 1) * D + d];
        const float u2 = U1[(m + 2) * D + d];
        const float u3 = U1[(m + 3) * D + d];
#pragma unroll
        for (int r = 0; r < TR; r++) {
            const float4 a4 = *(const float4*)(&sa[r][m]);
            acc[r] = fmaf(a4.x, u0, acc[r]);
            acc[r] = fmaf(a4.y, u1, acc[r]);
            acc[r] = fmaf(a4.z, u2, acc[r]);
            acc[r] = fmaf(a4.w, u3, acc[r]);
        }
    }
#pragma unroll
    for (int r = 0; r < TR; r++) sacc[quar][r][d] = acc[r];
    __syncthreads();

    {
        const int r = tid >> 7, dd = tid & 127;
        sy[r][dd] = fmaxf(sacc[0][r][dd] + sacc[1][r][dd] +
                          sacc[2][r][dd] + sacc[3][r][dd], 0.f);
    }
    __syncthreads();

    {
        const float init = quar ? 0.f : b4[d];
#pragma unroll
        for (int r = 0; r < TR; r++) acc[r] = init;
    }
    const int kk0 = quar * 32;
#pragma unroll 4
    for (int g4 = 0; g4 < 8; g4++) {
        const int k = kk0 + g4 * 4;
        const float u0 = U2[(k + 0) * D + d];
        const float u1 = U2[(k + 1) * D + d];
        const float u2 = U2[(k + 2) * D + d];
        const float u3 = U2[(k + 3) * D + d];
#pragma unroll
        for (int r = 0; r < TR; r++) {
            const float4 y4 = *(const float4*)(&sy[r][k]);
            acc[r] = fmaf(y4.x, u0, acc[r]);
            acc[r] = fmaf(y4.y, u1, acc[r]);
            acc[r] = fmaf(y4.z, u2, acc[r]);
            acc[r] = fmaf(y4.w, u3, acc[r]);
        }
    }
#pragma unroll
    for (int r = 0; r < TR; r++) sacc[quar][r][d] = acc[r];
    __syncthreads();

    const int w = tid >> 5, lane = tid & 31;
    if (w < TR) {
        float x[4];
        float s = 0.f, q = 0.f;
#pragma unroll
        for (int i = 0; i < 4; i++) {
            const int dd = lane + i * 32;
            x[i] = sa[w][dd] + sacc[0][w][dd] + sacc[1][w][dd] +
                   sacc[2][w][dd] + sacc[3][w][dd];
            s += x[i];
            q = fmaf(x[i], x[i], q);
        }
#pragma unroll
        for (int off = 16; off; off >>= 1) {
            s += __shfl_xor_sync(0xffffffffu, s, off);
            q += __shfl_xor_sync(0xffffffffu, q, off);
        }
        const float mu  = s * (1.f / 128.f);
        const float var = q * (1.f / 128.f) - mu * mu;
        const float inv = rsqrtf(var + 1e-5f);
#pragma unroll
        for (int i = 0; i < 4; i++) {
            const int dd = lane + i * 32;
            out[(rbase + w) * D + dd] = (x[i] - mu) * inv * gamma[dd] + beta[dd];
        }
    }
}

// ---------------------------------------------------------------------------
// Probe: trivial third launch. Shifts ncu's fixed capture slot (launch #4)
// onto gate_kernel so the next round's profile shows gate, not update.
// ---------------------------------------------------------------------------
__global__ void probe_kernel() {
    if (threadIdx.x == 0) g_probe = 1;
}

// ---------------------------------------------------------------------------
extern "C" void kernel_launch(void* const* d_in, const int* in_sizes, int n_in,
                              void* d_out, int out_size) {
    const float*        h     = (const float*)d_in[0];
    const float*        ef    = (const float*)d_in[1];
    const unsigned int* adj   = (const unsigned int*)d_in[2];
    const float*        W1    = (const float*)d_in[3];
    const float*        b1    = (const float*)d_in[4];
    const float*        W2    = (const float*)d_in[5];
    const float*        b2    = (const float*)d_in[6];
    const float*        U1    = (const float*)d_in[7];
    const float*        b3    = (const float*)d_in[8];
    const float*        U2    = (const float*)d_in[9];
    const float*        b4    = (const float*)d_in[10];
    const float*        gamma = (const float*)d_in[11];
    const float*        beta  = (const float*)d_in[12];
    float* out = (float*)d_out;

    gate_kernel<<<ROWS, 256>>>(h, ef, adj, W1, b1, W2, b2);
    update_kernel<<<ROWS / TR, 512>>>(h, U1, b3, U2, b4, gamma, beta, out);
    probe_kernel<<<1, 32>>>();
}

// round 15
// speedup vs baseline: 1.6080x; 1.6080x over previous
#include <cuda_runtime.h>
#include <cuda_fp16.h>
#include <math_constants.h>
#include <cstdint>

// Problem constants
#define ROWS 2048     // B*N
#define D    128
#define E    64
#define NJ   256
#define TR   8        // rows per block in update kernel (4-way split-k, 512 thr)
#define PITCH 144     // sT row pitch in bytes (128B data + 16B skew)

__device__ float g_agg[ROWS * 2 * D];   // per row: [agg_mean(128) | agg_max(128)]

__device__ __forceinline__ uint32_t pack_h2(float a, float b) {
    __half2 h = __floats2half2_rn(a, b);
    return *(uint32_t*)&h;
}

// D = A(16x16) * B(16x8) + D, fp16 in / fp32 acc. Emits HMMA.16816 on sm_103.
__device__ __forceinline__ void mma16816(float c[4], const uint32_t a[4],
                                         uint32_t b0, uint32_t b1) {
    asm volatile(
        "mma.sync.aligned.m16n8k16.row.col.f32.f16.f16.f32 "
        "{%0,%1,%2,%3}, {%4,%5,%6,%7}, {%8,%9}, {%0,%1,%2,%3};"
        : "+f"(c[0]), "+f"(c[1]), "+f"(c[2]), "+f"(c[3])
        : "r"(a[0]), "r"(a[1]), "r"(a[2]), "r"(a[3]), "r"(b0), "r"(b1));
}

// sigmoid(z + b2) given ha = 0.5*z + 0.5*b2   (1 MUFU)
__device__ __forceinline__ float sig_half(float ha) {
    float t;
    asm("tanh.approx.f32 %0, %1;" : "=f"(t) : "f"(ha));
    return fmaf(t, 0.5f, 0.5f);
}

__device__ __forceinline__ float tanh_ap(float x) {
    float t;
    asm("tanh.approx.f32 %0, %1;" : "=f"(t) : "f"(x));
    return t;
}

// ---------------------------------------------------------------------------
// Gate kernel — EXACT R13 version (39us validated). ONE row per CTA
// (grid=2048), 256 threads (8 warps). Warp w owns d-tile [16w,16w+16).
// ---------------------------------------------------------------------------
__global__ void __launch_bounds__(256)
gate_kernel(const float* __restrict__ h, const float* __restrict__ ef,
            const unsigned int* __restrict__ adj,
            const float* __restrict__ W1, const float* __restrict__ b1,
            const float* __restrict__ W2, const float* __restrict__ b2) {
    __shared__ __align__(16) char  sT[NJ * PITCH];   // fp16 T tile, skewed rows
    __shared__ __align__(16) float sE[NJ * 4];       // edge feats, float4/row
    __shared__ float sH[D];
    __shared__ float sPp[4][E];                      // P partials
    __shared__ float sP[E];
    __shared__ int   sJ[NJ];
    __shared__ int   sW[8];

    const int tid  = threadIdx.x;
    const int w    = tid >> 5;
    const int lane = tid & 31;
    const int g    = lane >> 2;      // groupID
    const int t4   = lane & 3;       // thread-in-group
    const int row  = blockIdx.x;

    // ---- issue ALL dram loads up front (overlap with compute below) ----
    const float* efr = ef + (size_t)row * (NJ * 3);
    const float e0 = efr[tid];
    const float e1 = efr[tid + 256];
    const float e2 = efr[tid + 512];
    const int   m0 = (adj[(size_t)row * NJ + tid] != 0u);
    if (tid < D) sH[tid] = h[(size_t)row * D + tid];

    // ballot per warp (j = tid exactly covers 0..255)
    const unsigned bal = __ballot_sync(0xffffffffu, m0);
    if (lane == 0) sW[w] = __popc(bal);

    // ---- A fragments: A[d][k] = W2[k][d], one m-tile per warp (L1/L2 hot) ----
    uint32_t afr[4][4];
    {
        const int d0 = w * 16 + g;
#pragma unroll
        for (int ks = 0; ks < 4; ks++) {
            const int k0 = ks * 16 + 2 * t4;
            afr[ks][0] = pack_h2(W2[k0 * D + d0],       W2[(k0 + 1) * D + d0]);
            afr[ks][1] = pack_h2(W2[k0 * D + d0 + 8],   W2[(k0 + 1) * D + d0 + 8]);
            afr[ks][2] = pack_h2(W2[(k0 + 8) * D + d0], W2[(k0 + 9) * D + d0]);
            afr[ks][3] = pack_h2(W2[(k0 + 8) * D + d0 + 8], W2[(k0 + 9) * D + d0 + 8]);
        }
    }
    int   dsl[2];
    float hb2[2];
#pragma unroll
    for (int i = 0; i < 2; i++) {
        dsl[i] = w * 16 + g + i * 8;
        hb2[i] = 0.5f * b2[dsl[i]];
    }

    // ---- stash ef into padded smem ----
    sE[(tid / 3) * 4 + (tid % 3)]                 = e0;
    sE[((tid + 256) / 3) * 4 + ((tid + 256) % 3)] = e1;
    sE[((tid + 512) / 3) * 4 + ((tid + 512) % 3)] = e2;

    // T-build constants (k-pair = lane)
    const int k0p = 2 * lane;
    const float2 w1e0 = *(const float2*)(W1 + 128 * E + k0p);
    const float2 w1e1 = *(const float2*)(W1 + 129 * E + k0p);
    const float2 w1e2 = *(const float2*)(W1 + 130 * E + k0p);

    __syncthreads();   // sH, sW ready

    // ---- P partials: thread (kk, part) does 32-d slice ----
    {
        const int kk = tid & 63, part = tid >> 6;
        const int db = part * 32;
        float p = 0.f;
#pragma unroll 8
        for (int d = 0; d < 32; d++)
            p = fmaf(sH[db + d], __ldg(&W1[(db + d) * E + kk]), p);
        sPp[part][kk] = p;
    }

    // ---- order-preserving compaction ----
    int base = 0, cnt = 0;
#pragma unroll
    for (int ww = 0; ww < 8; ww++) {
        if (ww < w) base += sW[ww];
        cnt += sW[ww];
    }
    if (m0) sJ[base + __popc(bal & ((1u << lane) - 1u))] = tid;
    __syncthreads();   // sPp, sJ ready

    if (tid < E)
        sP[tid] = b1[tid] + ((sPp[0][tid] + sPp[1][tid]) +
                             (sPp[2][tid] + sPp[3][tid]));
    __syncthreads();   // sP ready

    if (cnt == 0) {
        if (tid < D) {
            g_agg[(size_t)row * (2 * D) + tid]     = 0.f;
            g_agg[(size_t)row * (2 * D) + D + tid] = 0.f;
        }
        return;
    }

    // ---- T build: T[s][k] = relu(P[k] + e·W1e), fp16x2 per lane ----
    {
        const float2 P2 = *(const float2*)(sP + k0p);
        for (int s = w; s < cnt; s += 8) {
            const int j = sJ[s];
            const float4 e = *(const float4*)(sE + 4 * j);
            float v0 = fmaf(e.z, w1e2.x, fmaf(e.y, w1e1.x, fmaf(e.x, w1e0.x, P2.x)));
            float v1 = fmaf(e.z, w1e2.y, fmaf(e.y, w1e1.y, fmaf(e.x, w1e0.y, P2.y)));
            *(uint32_t*)(sT + s * PITCH + lane * 4) =
                pack_h2(fmaxf(v0, 0.f), fmaxf(v1, 0.f));
        }
    }
    __syncthreads();   // sT ready

    // ---- mma over j-tiles of 8 (4 HMMA per tile, scalar B loads) ----
    float st[2] = {0.f, 0.f};                          // sum of tanh
    float zx[2] = {-CUDART_INF_F, -CUDART_INF_F};
    float zn[2] = { CUDART_INF_F,  CUDART_INF_F};
    const int ntile = (cnt + 7) >> 3;
    const char* sTrow = sT + (size_t)g * PITCH;

    for (int jt = 0; jt < ntile; jt++) {
        float c0[4] = {0.f, 0.f, 0.f, 0.f};
        const char* tb = sTrow + jt * (8 * PITCH) + t4 * 4;
#pragma unroll
        for (int ks = 0; ks < 4; ks++) {
            const uint32_t b0 = *(const uint32_t*)(tb + ks * 32);
            const uint32_t b1r = *(const uint32_t*)(tb + ks * 32 + 16);
            mma16816(c0, afr[ks], b0, b1r);
        }
        const int s0 = jt * 8 + 2 * t4;
#define UPDZ(i, zz) do { const float _z = (zz); \
    st[i] += tanh_ap(fmaf(_z, 0.5f, hb2[i])); \
    zx[i] = fmaxf(zx[i], _z); zn[i] = fminf(zn[i], _z); } while (0)
        if (s0 < cnt)     { UPDZ(0, c0[0]); UPDZ(1, c0[2]); }
        if (s0 + 1 < cnt) { UPDZ(0, c0[1]); UPDZ(1, c0[3]); }
#undef UPDZ
    }

    // 4-lane (t4 group) reduction
#pragma unroll
    for (int off = 1; off <= 2; off <<= 1) {
#pragma unroll
        for (int i = 0; i < 2; i++) {
            st[i] += __shfl_xor_sync(0xffffffffu, st[i], off);
            zx[i] = fmaxf(zx[i], __shfl_xor_sync(0xffffffffu, zx[i], off));
            zn[i] = fminf(zn[i], __shfl_xor_sync(0xffffffffu, zn[i], off));
        }
    }
    if (t4 == 0) {
        const float cntf = (float)cnt;
#pragma unroll
        for (int i = 0; i < 2; i++) {
            const int d = dsl[i];
            const float hd = sH[d];
            const float sumg = fmaf(0.5f, st[i], 0.5f * cntf); // Σσ = ½Σtanh + ½cnt
            const float cm = hd * sumg / cntf;
            const float gx = sig_half(fmaf(zx[i], 0.5f, hb2[i]));
            const float gn = sig_half(fmaf(zn[i], 0.5f, hb2[i]));
            const float cx = (hd >= 0.f) ? hd * gx : hd * gn;
            g_agg[(size_t)row * (2 * D) + d]     = cm;
            g_agg[(size_t)row * (2 * D) + D + d] = cx;
        }
    }
}

// ---------------------------------------------------------------------------
// Update MLP + residual + LayerNorm — TR=8 rows/CTA, 512 threads, 4-way
// split-k (grid 256). Doubles FMA-per-LDG vs TR=4 to reduce L2-latency
// stall exposure. thread = (d = tid&127, quarter = tid>>7).
// ---------------------------------------------------------------------------
__global__ void __launch_bounds__(512)
update_kernel(const float* __restrict__ h,
              const float* __restrict__ U1, const float* __restrict__ b3,
              const float* __restrict__ U2, const float* __restrict__ b4,
              const float* __restrict__ gamma, const float* __restrict__ beta,
              float* __restrict__ out) {
    const int rbase = blockIdx.x * TR;
    const int tid  = threadIdx.x;
    const int d    = tid & 127;
    const int quar = tid >> 7;
    __shared__ __align__(16) float sa[TR][3 * D];     // [h | mean | max]  12KB
    __shared__ __align__(16) float sy[TR][D];         // relu hidden        4KB
    __shared__ __align__(16) float sacc[4][TR][D];    // split-k partials  16KB

    for (int idx = tid; idx < TR * 3 * D; idx += 512) {
        const int r = idx / (3 * D);
        const int m = idx % (3 * D);
        float v;
        if (m < D) v = h[(rbase + r) * D + m];
        else       v = g_agg[(size_t)(rbase + r) * (2 * D) + (m - D)];
        sa[r][m] = v;
    }
    __syncthreads();

    float acc[TR];
    // ---- GEMM1: y = relu(X @ U1 + b3); this quarter covers 96 k-values ----
    {
        const float init = quar ? 0.f : b3[d];
#pragma unroll
        for (int r = 0; r < TR; r++) acc[r] = init;
    }
    const int m0 = quar * 96;
#pragma unroll 2
    for (int g4 = 0; g4 < 24; g4++) {
        const int m = m0 + g4 * 4;
        const float u0 = U1[(m + 0) * D + d];
        const float u1 = U1[(m + 1) * D + d];
        const float u2 = U1[(m + 2) * D + d];
        const float u3 = U1[(m + 3) * D + d];
#pragma unroll
        for (int r = 0; r < TR; r++) {
            const float4 a4 = *(const float4*)(&sa[r][m]);
            acc[r] = fmaf(a4.x, u0, acc[r]);
            acc[r] = fmaf(a4.y, u1, acc[r]);
            acc[r] = fmaf(a4.z, u2, acc[r]);
            acc[r] = fmaf(a4.w, u3, acc[r]);
        }
    }
#pragma unroll
    for (int r = 0; r < TR; r++) sacc[quar][r][d] = acc[r];
    __syncthreads();

    // combine + relu (TR*D = 1024 elems, 2 per thread)
#pragma unroll
    for (int i = 0; i < 2; i++) {
        const int idx = tid + i * 512;
        const int r = idx >> 7, dd = idx & 127;
        sy[r][dd] = fmaxf(sacc[0][r][dd] + sacc[1][r][dd] +
                          sacc[2][r][dd] + sacc[3][r][dd], 0.f);
    }
    __syncthreads();

    // ---- GEMM2: upd = y @ U2 + b4; this quarter covers 32 k-values ----
    {
        const float init = quar ? 0.f : b4[d];
#pragma unroll
        for (int r = 0; r < TR; r++) acc[r] = init;
    }
    const int kk0 = quar * 32;
#pragma unroll 2
    for (int g4 = 0; g4 < 8; g4++) {
        const int k = kk0 + g4 * 4;
        const float u0 = U2[(k + 0) * D + d];
        const float u1 = U2[(k + 1) * D + d];
        const float u2 = U2[(k + 2) * D + d];
        const float u3 = U2[(k + 3) * D + d];
#pragma unroll
        for (int r = 0; r < TR; r++) {
            const float4 y4 = *(const float4*)(&sy[r][k]);
            acc[r] = fmaf(y4.x, u0, acc[r]);
            acc[r] = fmaf(y4.y, u1, acc[r]);
            acc[r] = fmaf(y4.z, u2, acc[r]);
            acc[r] = fmaf(y4.w, u3, acc[r]);
        }
    }
#pragma unroll
    for (int r = 0; r < TR; r++) sacc[quar][r][d] = acc[r];
    __syncthreads();

    // ---- residual + LayerNorm: warp w owns row w (w < TR=8) ----
    const int w = tid >> 5, lane = tid & 31;
    if (w < TR) {
        float x[4];
        float s = 0.f, q = 0.f;
#pragma unroll
        for (int i = 0; i < 4; i++) {
            const int dd = lane + i * 32;
            x[i] = sa[w][dd] + sacc[0][w][dd] + sacc[1][w][dd] +
                   sacc[2][w][dd] + sacc[3][w][dd];
            s += x[i];
            q = fmaf(x[i], x[i], q);
        }
#pragma unroll
        for (int off = 16; off; off >>= 1) {
            s += __shfl_xor_sync(0xffffffffu, s, off);
            q += __shfl_xor_sync(0xffffffffu, q, off);
        }
        const float mu  = s * (1.f / 128.f);
        const float var = q * (1.f / 128.f) - mu * mu;
        const float inv = rsqrtf(var + 1e-5f);
#pragma unroll
        for (int i = 0; i < 4; i++) {
            const int dd = lane + i * 32;
            out[(rbase + w) * D + dd] = (x[i] - mu) * inv * gamma[dd] + beta[dd];
        }
    }
}

// ---------------------------------------------------------------------------
extern "C" void kernel_launch(void* const* d_in, const int* in_sizes, int n_in,
                              void* d_out, int out_size) {
    const float*        h     = (const float*)d_in[0];
    const float*        ef    = (const float*)d_in[1];
    const unsigned int* adj   = (const unsigned int*)d_in[2];
    const float*        W1    = (const float*)d_in[3];
    const float*        b1    = (const float*)d_in[4];
    const float*        W2    = (const float*)d_in[5];
    const float*        b2    = (const float*)d_in[6];
    const float*        U1    = (const float*)d_in[7];
    const float*        b3    = (const float*)d_in[8];
    const float*        U2    = (const float*)d_in[9];
    const float*        b4    = (const float*)d_in[10];
    const float*        gamma = (const float*)d_in[11];
    const float*        beta  = (const float*)d_in[12];
    float* out = (float*)d_out;

    gate_kernel<<<ROWS, 256>>>(h, ef, adj, W1, b1, W2, b2);
    update_kernel<<<ROWS / TR, 512>>>(h, U1, b3, U2, b4, gamma, beta, out);
}